// round 12
// baseline (speedup 1.0000x reference)
#include <cuda_runtime.h>
#include <cuda_bf16.h>
#include <stdint.h>

// ============================================================================
// BFP8 quantized 3x3 conv (stride 1, pad 1) == GEMM M=100352, N=256, K=1152
// Round 12: overlap quant_a with gemm in ONE mega-kernel.
//   K1: quantize weight -> s8 + scales; ALSO resets per-tile flags.
//   K2 (mega): 1-D grid, 8624 blocks: 7056 producer blocks (quantize one
//       m-tile's A 64-blocks, then release-increment g_cnt[tile]) interleaved
//       with 1568 consumer blocks (128x128 IMMA gemm; acquire-spin until
//       g_cnt[tile]==9). In-order CTA dispatch + producers-before-consumers
//       in linear order => no deadlock.
// ============================================================================

#define C_IN      128
#define C_OUT     256
#define HWDIM     56
#define IMG_PIX   3136
#define K_TOTAL   1152
#define M_TOTAL   100352
#define NTILES    784
#define NBLK      18
#define LAG       48

#define QMAGIC    12582912.0f          // 1.5 * 2^23
#define QCLAMP    12583039.0f          // QMAGIC + 127

__device__ __align__(16) int8_t g_wq8[C_OUT * K_TOTAL];
__device__ float   g_sw[NBLK * C_OUT];
__device__ __align__(16) int8_t g_qa8[(size_t)M_TOTAL * K_TOTAL];   // 110 MB
__device__ float   g_sa[(size_t)NBLK * M_TOTAL];
__device__ unsigned g_cnt[NTILES];

// ---------------------------------------------------------------------------
__device__ __forceinline__ uint32_t cvta_smem(const void* p) {
    uint32_t a;
    asm("{ .reg .u64 t; cvta.to.shared.u64 t, %1; cvt.u32.u64 %0, t; }"
        : "=r"(a) : "l"(p));
    return a;
}
__device__ __forceinline__ void ldsm_x4(uint32_t* d, uint32_t addr) {
    asm volatile("ldmatrix.sync.aligned.m8n8.x4.shared.b16 {%0,%1,%2,%3}, [%4];"
                 : "=r"(d[0]), "=r"(d[1]), "=r"(d[2]), "=r"(d[3]) : "r"(addr));
}
__device__ __forceinline__ void imma_init(int* d, const uint32_t* a,
                                          uint32_t b0, uint32_t b1) {
    asm volatile(
        "mma.sync.aligned.m16n8k32.row.col.s32.s8.s8.s32 "
        "{%0,%1,%2,%3}, {%4,%5,%6,%7}, {%8,%9}, {%10,%10,%10,%10};"
        : "=r"(d[0]), "=r"(d[1]), "=r"(d[2]), "=r"(d[3])
        : "r"(a[0]), "r"(a[1]), "r"(a[2]), "r"(a[3]),
          "r"(b0), "r"(b1), "r"(0));
}
__device__ __forceinline__ void imma_acc(int* d, const uint32_t* a,
                                         uint32_t b0, uint32_t b1) {
    asm volatile(
        "mma.sync.aligned.m16n8k32.row.col.s32.s8.s8.s32 "
        "{%0,%1,%2,%3}, {%4,%5,%6,%7}, {%8,%9}, {%0,%1,%2,%3};"
        : "+r"(d[0]), "+r"(d[1]), "+r"(d[2]), "+r"(d[3])
        : "r"(a[0]), "r"(a[1]), "r"(a[2]), "r"(a[3]), "r"(b0), "r"(b1));
}
__device__ __forceinline__ void cp_async16(uint32_t dst, const void* src) {
    asm volatile("cp.async.cg.shared.global [%0], [%1], 16;" :: "r"(dst), "l"(src));
}
__device__ __forceinline__ void cp_commit() {
    asm volatile("cp.async.commit_group;");
}
template <int N>
__device__ __forceinline__ void cp_wait() {
    asm volatile("cp.async.wait_group %0;" :: "n"(N));
}

__device__ __forceinline__ int block_exp(float mx) {
    mx = fmaxf(mx, 1e-38f);
    return ((__float_as_int(mx) >> 23) & 255) - 127;
}
__device__ __forceinline__ uint32_t qmagic(float x, float inv) {
    return __float_as_uint(fminf(fmaf(x, inv, QMAGIC), QCLAMP));
}
__device__ __forceinline__ uint32_t qpack4(float v0, float v1, float v2,
                                           float v3, float inv) {
    uint32_t u0 = qmagic(v0, inv), u1 = qmagic(v1, inv);
    uint32_t u2 = qmagic(v2, inv), u3 = qmagic(v3, inv);
    return __byte_perm(__byte_perm(u0, u1, 0x0040),
                       __byte_perm(u2, u3, 0x0040), 0x5410);
}

// ---------------------------------------------------------------------------
// Kernel 1: quantize weight (warp per (row, 64-block)) + reset tile flags.
// grid (18, 256), 32 threads.
// ---------------------------------------------------------------------------
__global__ void quant_w8_kernel(const float* __restrict__ w) {
    const int b    = blockIdx.x;
    const int row  = blockIdx.y;
    const int lane = threadIdx.x;

    if (b == 0) {                       // 256 blocks x 32 lanes reset flags
        int idx = row * 32 + lane;
        if (idx < NTILES) g_cnt[idx] = 0;
    }

    const float* src = w + (size_t)row * K_TOTAL + b * 64;
    float a0 = __ldg(src + lane);
    float a1 = __ldg(src + 32 + lane);
    float mx = fmaxf(fabsf(a0), fabsf(a1));
#pragma unroll
    for (int o = 16; o > 0; o >>= 1)
        mx = fmaxf(mx, __shfl_xor_sync(0xFFFFFFFFu, mx, o));
    int e = block_exp(mx);
    float inv = __int_as_float((133 - e) << 23);
    int8_t* dst = g_wq8 + (size_t)row * K_TOTAL + b * 64;
    dst[lane]      = (int8_t)(qmagic(a0, inv) & 0xFF);
    dst[32 + lane] = (int8_t)(qmagic(a1, inv) & 0xFF);
    if (lane == 0) g_sw[b * C_OUT + row] = __int_as_float((e + 121) << 23);
}

// ---------------------------------------------------------------------------
// Producer: quantize one (m-tile, y) slice of im2col(A). 256 threads.
// ---------------------------------------------------------------------------
template <int S>
__device__ __forceinline__ void gather64(const float* __restrict__ pix,
                                         uint32_t vmask, float* v, float* mx4) {
#pragma unroll
    for (int e = 0; e < 64; ++e) {
        const int u   = S + e;
        const int ci  = u / 9;
        const int tap = u % 9;
        const int off = ci * IMG_PIX + (tap / 3) * HWDIM + (tap % 3);
        float val = ((vmask >> tap) & 1u) ? __ldg(pix + off) : 0.0f;
        v[e] = val;
        mx4[e & 3] = fmaxf(mx4[e & 3], fabsf(val));
    }
}

__device__ void producer_body(const float* __restrict__ inp, int tile, int y) {
    const int tid = threadIdx.x;
    const int r   = tid & 127;
    const int h   = tid >> 7;
    const int b   = 2 * y + h;
    const int m   = tile * 128 + r;
    const int c0  = (b * 64) / 9;

    const int ni = m / IMG_PIX;
    const int p  = m - ni * IMG_PIX;
    const int ho = p / HWDIM;
    const int wo = p - ho * HWDIM;
    const float* pix = inp + ((size_t)ni * C_IN + c0) * IMG_PIX
                       + ho * HWDIM + wo - 57;

    uint32_t vmask = 0;
#pragma unroll
    for (int kh = 0; kh < 3; ++kh)
#pragma unroll
        for (int kw = 0; kw < 3; ++kw) {
            int hh = ho + kh - 1, ww = wo + kw - 1;
            if ((unsigned)hh < (unsigned)HWDIM && (unsigned)ww < (unsigned)HWDIM)
                vmask |= 1u << (kh * 3 + kw);
        }

    float v[64];
    float mx4[4] = {0.0f, 0.0f, 0.0f, 0.0f};
    switch (y) {
        case 0: if (h) gather64<1>(pix, vmask, v, mx4); else gather64<0>(pix, vmask, v, mx4); break;
        case 1: if (h) gather64<3>(pix, vmask, v, mx4); else gather64<2>(pix, vmask, v, mx4); break;
        case 2: if (h) gather64<5>(pix, vmask, v, mx4); else gather64<4>(pix, vmask, v, mx4); break;
        case 3: if (h) gather64<7>(pix, vmask, v, mx4); else gather64<6>(pix, vmask, v, mx4); break;
        case 4: if (h) gather64<0>(pix, vmask, v, mx4); else gather64<8>(pix, vmask, v, mx4); break;
        case 5: if (h) gather64<2>(pix, vmask, v, mx4); else gather64<1>(pix, vmask, v, mx4); break;
        case 6: if (h) gather64<4>(pix, vmask, v, mx4); else gather64<3>(pix, vmask, v, mx4); break;
        case 7: if (h) gather64<6>(pix, vmask, v, mx4); else gather64<5>(pix, vmask, v, mx4); break;
        default:if (h) gather64<8>(pix, vmask, v, mx4); else gather64<7>(pix, vmask, v, mx4); break;
    }
    float mx = fmaxf(fmaxf(mx4[0], mx4[1]), fmaxf(mx4[2], mx4[3]));

    int e = block_exp(mx);
    float inv = __int_as_float((133 - e) << 23);

    uint32_t pk[16];
#pragma unroll
    for (int i = 0; i < 16; ++i)
        pk[i] = qpack4(v[4*i], v[4*i+1], v[4*i+2], v[4*i+3], inv);

    uint4* dst = reinterpret_cast<uint4*>(g_qa8 + (size_t)m * K_TOTAL + b * 64);
#pragma unroll
    for (int i = 0; i < 4; ++i)
        dst[i] = make_uint4(pk[4*i], pk[4*i+1], pk[4*i+2], pk[4*i+3]);
    g_sa[(size_t)b * M_TOTAL + m] = __int_as_float((e + 121) << 23);

    // publish: all stores of this block done -> release increment of tile flag
    __syncthreads();
    if (tid == 0) {
        __threadfence();
        asm volatile("red.release.gpu.global.add.u32 [%0], %1;"
                     :: "l"(&g_cnt[tile]), "r"(1u) : "memory");
    }
}

// ---------------------------------------------------------------------------
// Consumer: 128x128 IMMA gemm for (tile, ntile). 256 threads, 102.9KB smem.
// ---------------------------------------------------------------------------
#define A_SZ      16384
#define B_SZ      16384
#define STAGE     (A_SZ + B_SZ)
#define NSTAGE    3
#define SCALE_OFF (NSTAGE * STAGE)
#define SA_BYTES  (NBLK * 128)
#define K3_SMEM   (SCALE_OFF + 2 * SA_BYTES)
#define C_STRIDE  132

__device__ void consumer_body(const float* __restrict__ bias,
                              float* __restrict__ out, int tile, int ntile) {
    extern __shared__ __align__(16) char smem[];
    const uint32_t smem_u = cvta_smem(smem);
    uint8_t* sSA8 = reinterpret_cast<uint8_t*>(smem + SCALE_OFF);
    uint8_t* sSW8 = sSA8 + SA_BYTES;

    const int tid  = threadIdx.x;

    // ---- wait for this tile's 9 producer blocks (acquire) ----
    if (tid == 0) {
        unsigned vcnt;
        do {
            asm volatile("ld.acquire.gpu.global.u32 %0, [%1];"
                         : "=r"(vcnt) : "l"(&g_cnt[tile]));
            if (vcnt < 9u) __nanosleep(256);
        } while (vcnt < 9u);
    }
    __syncthreads();

    const int wid  = tid >> 5;
    const int lane = tid & 31;
    const int warp_m = wid & 3;
    const int warp_n = wid >> 2;
    const int m_base = tile * 128;

    for (int i = tid; i < SA_BYTES; i += 256)
        sSA8[i] = (uint8_t)(__float_as_uint(
            g_sa[(size_t)(i >> 7) * M_TOTAL + m_base + (i & 127)]) >> 23);
    for (int i = tid; i < SA_BYTES; i += 256)
        sSW8[i] = (uint8_t)(__float_as_uint(
            g_sw[(i >> 7) * C_OUT + ntile * 128 + (i & 127)]) >> 23);

    const int lr = tid >> 1;
    const int jh = (tid & 1) * 4;
    const uint32_t lkey = (uint32_t)(lr & 7);
    const int8_t* a_src = g_qa8 + (size_t)(m_base + lr) * K_TOTAL;
    const int8_t* b_src = g_wq8 + (size_t)(ntile * 128 + lr) * K_TOTAL;

    auto load_stage = [&](int kc, int s) {
        const uint32_t st = smem_u + s * STAGE;
        const int ko = kc * 128;
#pragma unroll
        for (int i = 0; i < 4; ++i) {
            uint32_t u = (uint32_t)(jh + i);
            uint32_t sw = ((u ^ lkey) << 4) + (uint32_t)(lr * 128);
            cp_async16(st + sw, a_src + ko + u * 16);
            cp_async16(st + A_SZ + sw, b_src + ko + u * 16);
        }
        cp_commit();
    };

    const uint32_t keyA = (uint32_t)(lane & 7);
    const uint32_t hiA  = (uint32_t)(lane >> 4);
    const uint32_t baseA = (uint32_t)((warp_m * 32 + (lane & 7)
                                       + ((lane >> 3) & 1) * 8) * 128);
    const uint32_t hiB  = (uint32_t)((lane >> 3) & 1);
    const uint32_t baseB = (uint32_t)(A_SZ + (warp_n * 64 + (lane & 7)
                                              + (lane >> 4) * 8) * 128);
    const int rs0 = warp_m * 32 + (lane >> 2);
    const int cs0 = warp_n * 64 + 2 * (lane & 3);

    float acc[16][4];
#pragma unroll
    for (int i = 0; i < 16; ++i)
#pragma unroll
        for (int j = 0; j < 4; ++j) acc[i][j] = 0.0f;

    load_stage(0, 0);
    load_stage(1, 1);

    int s = 0;
    for (int kc = 0; kc < 9; ++kc) {
        cp_wait<1>();
        __syncthreads();
        const uint32_t sb = smem_u + s * STAGE;

#pragma unroll
        for (int blk = 0; blk < 2; ++blk) {
            const int gb = kc * 2 + blk;
            const float sa0 = __uint_as_float((uint32_t)sSA8[gb * 128 + rs0] << 23);
            const float sa1 = __uint_as_float((uint32_t)sSA8[gb * 128 + rs0 + 8] << 23);
            const float sa2 = __uint_as_float((uint32_t)sSA8[gb * 128 + rs0 + 16] << 23);
            const float sa3 = __uint_as_float((uint32_t)sSA8[gb * 128 + rs0 + 24] << 23);

            uint32_t a[2][2][4];
#pragma unroll
            for (int mt = 0; mt < 2; ++mt)
#pragma unroll
                for (int ks = 0; ks < 2; ++ks)
                    ldsm_x4(a[mt][ks], sb + baseA + mt * 2048
                            + ((((uint32_t)(blk * 4 + ks * 2) + hiA) ^ keyA) << 4));

#pragma unroll
            for (int ntp = 0; ntp < 4; ++ntp) {
                uint32_t b0[4], b1[4];
                ldsm_x4(b0, sb + baseB + ntp * 2048
                        + ((((uint32_t)(blk * 4) + hiB) ^ keyA) << 4));
                ldsm_x4(b1, sb + baseB + ntp * 2048
                        + ((((uint32_t)(blk * 4 + 2) + hiB) ^ keyA) << 4));
                const float sw0 = __uint_as_float(
                    (uint32_t)sSW8[gb * 128 + cs0 + ntp * 16] << 23);
                const float sw1 = __uint_as_float(
                    (uint32_t)sSW8[gb * 128 + cs0 + ntp * 16 + 1] << 23);
                const float sw2 = __uint_as_float(
                    (uint32_t)sSW8[gb * 128 + cs0 + ntp * 16 + 8] << 23);
                const float sw3 = __uint_as_float(
                    (uint32_t)sSW8[gb * 128 + cs0 + ntp * 16 + 9] << 23);
#pragma unroll
                for (int mt = 0; mt < 2; ++mt) {
                    const float ra = (mt == 0) ? sa0 : sa2;
                    const float rb = (mt == 0) ? sa1 : sa3;
#pragma unroll
                    for (int nf = 0; nf < 2; ++nf) {
                        int t[4];
                        imma_init(t, a[mt][0], b0[nf * 2], b0[nf * 2 + 1]);
                        imma_acc (t, a[mt][1], b1[nf * 2], b1[nf * 2 + 1]);
                        const float ca = nf ? sw2 : sw0;
                        const float cb = nf ? sw3 : sw1;
                        float* A_ = acc[mt * 8 + ntp * 2 + nf];
                        A_[0] += (ra * ca) * __int2float_rn(t[0]);
                        A_[1] += (ra * cb) * __int2float_rn(t[1]);
                        A_[2] += (rb * ca) * __int2float_rn(t[2]);
                        A_[3] += (rb * cb) * __int2float_rn(t[3]);
                    }
                }
            }
        }

        if (kc + 2 < 9) load_stage(kc + 2, (s + 2 >= NSTAGE) ? s - 1 : s + 2);
        else cp_commit();
        if (++s == NSTAGE) s = 0;
    }

    __syncthreads();
    float* sC = reinterpret_cast<float*>(smem);
#pragma unroll
    for (int mt = 0; mt < 2; ++mt)
#pragma unroll
        for (int nt = 0; nt < 8; ++nt) {
            int rr = warp_m * 32 + mt * 16 + (lane >> 2);
            int cc = warp_n * 64 + nt * 8 + 2 * (lane & 3);
            float* f = acc[mt * 8 + nt];
            sC[cc * C_STRIDE + rr]           = f[0];
            sC[(cc + 1) * C_STRIDE + rr]     = f[1];
            sC[cc * C_STRIDE + rr + 8]       = f[2];
            sC[(cc + 1) * C_STRIDE + rr + 8] = f[3];
        }
    __syncthreads();

#pragma unroll
    for (int j = 0; j < 4; ++j) {
        int rr = j * 32 + lane;
        int mm = m_base + rr;
        int ni2 = mm / IMG_PIX;
        int pp  = mm - ni2 * IMG_PIX;
        float* ob = out + (size_t)ni2 * (C_OUT * IMG_PIX) + pp;
#pragma unroll 4
        for (int i = 0; i < 16; ++i) {
            int cl = wid * 16 + i;
            int co = ntile * 128 + cl;
            ob[(size_t)co * IMG_PIX] = sC[cl * C_STRIDE + rr] + __ldg(bias + co);
        }
    }
}

// ---------------------------------------------------------------------------
// Mega kernel: interleaved producers and consumers, 1-D grid of 8624 blocks.
//   [0, 9*LAG)                : producers, tiles 0..LAG-1
//   [9*LAG, 9*LAG+11*(784-LAG)): groups of 11 = 9 producers(tile LAG+g)
//                                           + 2 consumers(tile g)
//   tail                      : 2*LAG consumers for tiles 784-LAG..783
// ---------------------------------------------------------------------------
#define MEGA_BLOCKS (9 * NTILES + 2 * NTILES)   // 8624

__global__ __launch_bounds__(256, 2)
void mega_kernel(const float* __restrict__ inp,
                 const float* __restrict__ bias,
                 float* __restrict__ out) {
    const int bid = blockIdx.x;
    const int mid_end = 9 * LAG + 11 * (NTILES - LAG);

    if (bid < 9 * LAG) {
        producer_body(inp, bid / 9, bid % 9);
    } else if (bid < mid_end) {
        int g = bid - 9 * LAG;
        int grp = g / 11, rem = g - grp * 11;
        if (rem < 9) producer_body(inp, LAG + grp, rem);
        else         consumer_body(bias, out, grp, rem - 9);
    } else {
        int g = bid - mid_end;
        consumer_body(bias, out, NTILES - LAG + (g >> 1), g & 1);
    }
}

// ---------------------------------------------------------------------------
extern "C" void kernel_launch(void* const* d_in, const int* in_sizes, int n_in,
                              void* d_out, int out_size) {
    (void)in_sizes; (void)n_in; (void)out_size;
    const float* inp  = (const float*)d_in[0];
    const float* w    = (const float*)d_in[1];
    const float* bias = (const float*)d_in[2];
    float* out = (float*)d_out;

    cudaFuncSetAttribute(mega_kernel,
                         cudaFuncAttributeMaxDynamicSharedMemorySize, K3_SMEM);

    quant_w8_kernel<<<dim3(NBLK, C_OUT, 1), 32>>>(w);   // + flag reset
    mega_kernel<<<MEGA_BLOCKS, 256, K3_SMEM>>>(inp, bias, out);
}